// round 4
// baseline (speedup 1.0000x reference)
#include <cuda_runtime.h>

#define NELEM 16384
#define SORT_THREADS 1024
#define EPT 16            // elements per thread in sort block (16384/1024)

// Scratch (device globals; no allocations allowed)
__device__ float g_sorted_x[NELEM];
__device__ float g_sorted_y[NELEM];
__device__ float g_partials[128];

// ---------------------------------------------------------------------------
// Kernel 1: bitonic sort of one 16384-float array per block (grid = 2).
// Hybrid: strides j>=16 via shared memory; strides j<=8 in registers on each
// thread's contiguous 16-element chunk (no smem traffic, no barriers inside).
// ---------------------------------------------------------------------------
__global__ void bitonic_sort_kernel(const float* __restrict__ x,
                                    const float* __restrict__ y) {
    extern __shared__ float s[];
    const float* in  = (blockIdx.x == 0) ? x : y;
    float*       out = (blockIdx.x == 0) ? g_sorted_x : g_sorted_y;
    const int t = threadIdx.x;

    // Load to shared
#pragma unroll
    for (int i = 0; i < EPT; i++)
        s[t + i * SORT_THREADS] = in[t + i * SORT_THREADS];
    __syncthreads();

    // --- k = 2..16 entirely in registers (all pair strides < 16) ---
    {
        const int base = t * EPT;
        float r[EPT];
        float4* sv = reinterpret_cast<float4*>(&s[base]);
#pragma unroll
        for (int q = 0; q < EPT / 4; q++) {
            float4 v = sv[q];
            r[q * 4 + 0] = v.x; r[q * 4 + 1] = v.y;
            r[q * 4 + 2] = v.z; r[q * 4 + 3] = v.w;
        }
#pragma unroll
        for (unsigned k = 2; k <= 16; k <<= 1) {
#pragma unroll
            for (unsigned j = k >> 1; j >= 1; j >>= 1) {
#pragma unroll
                for (int q = 0; q < EPT; q++) {
                    if ((q & j) == 0) {
                        const int p = q | j;
                        const bool up = (((base + q) & k) == 0);
                        float a = r[q], b = r[p];
                        if ((a > b) == up) { r[q] = b; r[p] = a; }
                    }
                }
            }
        }
#pragma unroll
        for (int q = 0; q < EPT / 4; q++) {
            float4 v;
            v.x = r[q * 4 + 0]; v.y = r[q * 4 + 1];
            v.z = r[q * 4 + 2]; v.w = r[q * 4 + 3];
            sv[q] = v;
        }
    }
    __syncthreads();

    // --- k = 32..16384 ---
    for (unsigned k = 32; k <= NELEM; k <<= 1) {
        // shared-memory stages: j = k/2 down to 16
        for (unsigned j = k >> 1; j >= 16; j >>= 1) {
#pragma unroll
            for (int it = 0; it < EPT; it++) {
                const int w = t + it * SORT_THREADS;
                const unsigned ixj = (unsigned)w ^ j;
                if (ixj > (unsigned)w) {
                    const bool up = ((w & k) == 0);
                    float a = s[w], b = s[ixj];
                    if ((a > b) == up) { s[w] = b; s[ixj] = a; }
                }
            }
            __syncthreads();
        }
        // register tail: j = 8,4,2,1 within each thread's contiguous chunk
        {
            const int base = t * EPT;
            float r[EPT];
            float4* sv = reinterpret_cast<float4*>(&s[base]);
#pragma unroll
            for (int q = 0; q < EPT / 4; q++) {
                float4 v = sv[q];
                r[q * 4 + 0] = v.x; r[q * 4 + 1] = v.y;
                r[q * 4 + 2] = v.z; r[q * 4 + 3] = v.w;
            }
            const bool up = ((base & k) == 0);  // k >= 32: uniform over the chunk
#pragma unroll
            for (unsigned j = 8; j >= 1; j >>= 1) {
#pragma unroll
                for (int q = 0; q < EPT; q++) {
                    if ((q & j) == 0) {
                        const int p = q | j;
                        float a = r[q], b = r[p];
                        if ((a > b) == up) { r[q] = b; r[p] = a; }
                    }
                }
            }
#pragma unroll
            for (int q = 0; q < EPT / 4; q++) {
                float4 v;
                v.x = r[q * 4 + 0]; v.y = r[q * 4 + 1];
                v.z = r[q * 4 + 2]; v.w = r[q * 4 + 3];
                sv[q] = v;
            }
        }
        __syncthreads();
    }

    // Store sorted array
#pragma unroll
    for (int i = 0; i < EPT; i++)
        out[t + i * SORT_THREADS] = s[t + i * SORT_THREADS];
}

// ---------------------------------------------------------------------------
// Kernel 2: 32768 nearest-neighbor lookups + deterministic block sums.
// gid < NELEM  : value = sorted_x[gid], search sorted_y  (cd_xy contribution)
// gid >= NELEM : value = sorted_y[gid-N], search sorted_x (cd_yx contribution)
// Uniform binary search: exact for power-of-two N, all indices provably
// in-bounds (lo+step-1 <= 16383 in-loop; final check at lo <= 16383).
// ---------------------------------------------------------------------------
__global__ void chamfer_search_kernel() {
    const int gid = blockIdx.x * blockDim.x + threadIdx.x;  // 0..32767
    const bool diry = (gid >= NELEM);
    const int idx = diry ? (gid - NELEM) : gid;

    const float v = diry ? g_sorted_y[idx] : g_sorted_x[idx];
    const float* __restrict__ a = diry ? g_sorted_x : g_sorted_y;

    // lo = count of elements < v  (lower-bound index, 0..16384)
    int lo = 0;
#pragma unroll
    for (int step = NELEM / 2; step >= 1; step >>= 1) {
        if (a[lo + step - 1] < v) lo += step;   // index <= 16383 always
    }
    if (a[lo] < v) lo++;                        // lo was <= 16383 here

    float d = 3.4e38f;
    if (lo < NELEM) d = fabsf(a[lo] - v);
    if (lo > 0)     d = fminf(d, fabsf(v - a[lo - 1]));

    // deterministic block reduction
#pragma unroll
    for (int o = 16; o; o >>= 1) d += __shfl_xor_sync(0xffffffffu, d, o);
    __shared__ float ws[8];
    const int wid = threadIdx.x >> 5;
    if ((threadIdx.x & 31) == 0) ws[wid] = d;
    __syncthreads();
    if (threadIdx.x == 0) {
        float sum = 0.f;
#pragma unroll
        for (int i = 0; i < 8; i++) sum += ws[i];
        g_partials[blockIdx.x] = sum;
    }
}

// ---------------------------------------------------------------------------
// Kernel 3: reduce 128 partials and write the scalar loss.
// ALPHA = 0.5, n = m = 16384 -> result = 0.5 * (sx + sy) / 16384.
// ---------------------------------------------------------------------------
__global__ void finalize_kernel(float* __restrict__ out) {
    const int t = threadIdx.x;  // 128 threads
    float v = g_partials[t];
#pragma unroll
    for (int o = 16; o; o >>= 1) v += __shfl_xor_sync(0xffffffffu, v, o);
    __shared__ float ws[4];
    if ((t & 31) == 0) ws[t >> 5] = v;
    __syncthreads();
    if (t == 0) {
        const float sx = ws[0] + ws[1];
        const float sy = ws[2] + ws[3];
        out[0] = 0.5f * (sx + sy) * (1.0f / 16384.0f);
    }
}

// ---------------------------------------------------------------------------
extern "C" void kernel_launch(void* const* d_in, const int* in_sizes, int n_in,
                              void* d_out, int out_size) {
    const float* x = (const float*)d_in[0];
    const float* y = (const float*)d_in[1];
    float* out = (float*)d_out;

    // 64KB dynamic smem for the sort (opt-in above 48KB); attribute setting is
    // not a stream op — legal during graph capture, no allocation involved.
    cudaFuncSetAttribute(bitonic_sort_kernel,
                         cudaFuncAttributeMaxDynamicSharedMemorySize,
                         NELEM * (int)sizeof(float));

    bitonic_sort_kernel<<<2, SORT_THREADS, NELEM * sizeof(float)>>>(x, y);
    chamfer_search_kernel<<<128, 256>>>();
    finalize_kernel<<<1, 128>>>(out);
}

// round 5
// speedup vs baseline: 2.2960x; 2.2960x over previous
#include <cuda_runtime.h>

#define NELEM 16384
#define NB 8192                       // buckets per array (power of two)
#define RANGE_LO (-6.0f)
#define RANGE_HI (6.0f)
#define BW ((RANGE_HI - RANGE_LO) / (float)NB)
#define INV_BW ((float)NB / (RANGE_HI - RANGE_LO))

// Scratch (device globals; no allocations allowed).
// Index [0] = x-array structures, [1] = y-array structures.
__device__ int   g_cnt[2][NB];
__device__ int   g_off[2][NB + 1];
__device__ int   g_cur[2][NB];
__device__ float g_bval[2][NELEM];
__device__ float g_partials[128];

__device__ __forceinline__ int bucket_of(float v) {
    int b = (int)((v - RANGE_LO) * INV_BW);
    return min(max(b, 0), NB - 1);    // clamp outliers into end buckets (bounds stay valid)
}

// ---------------------------------------------------------------------------
// 1) Zero counters (graph replays reuse the globals — must reset every call)
// ---------------------------------------------------------------------------
__global__ void init_kernel() {
    const int i = blockIdx.x * blockDim.x + threadIdx.x;   // 0..8191
    if (i < NB) { g_cnt[0][i] = 0; g_cnt[1][i] = 0; }
}

// ---------------------------------------------------------------------------
// 2) Histogram both arrays (32768 threads, spread atomics)
// ---------------------------------------------------------------------------
__global__ void hist_kernel(const float* __restrict__ x,
                            const float* __restrict__ y) {
    const int i = blockIdx.x * blockDim.x + threadIdx.x;   // 0..32767
    const int a = (i >= NELEM);
    const float v = a ? y[i - NELEM] : x[i];
    atomicAdd(&g_cnt[a][bucket_of(v)], 1);
}

// ---------------------------------------------------------------------------
// 3) Exclusive prefix sum over 8192 counts per array (grid=2, 1024 threads).
//    Writes bucket offsets and initializes scatter cursors.
// ---------------------------------------------------------------------------
__global__ void prefix_kernel() {
    const int a = blockIdx.x;
    const int t = threadIdx.x;
    const int lane = t & 31, wid = t >> 5;

    int c[8];
    int s = 0;
#pragma unroll
    for (int i = 0; i < 8; i++) { c[i] = g_cnt[a][t * 8 + i]; s += c[i]; }

    // inclusive warp scan of per-thread sums
    int incl = s;
#pragma unroll
    for (int o = 1; o < 32; o <<= 1) {
        int n = __shfl_up_sync(0xffffffffu, incl, o);
        if (lane >= o) incl += n;
    }
    __shared__ int wsum[32];
    if (lane == 31) wsum[wid] = incl;
    __syncthreads();
    if (wid == 0) {
        int wv = wsum[lane];
        int wi = wv;
#pragma unroll
        for (int o = 1; o < 32; o <<= 1) {
            int n = __shfl_up_sync(0xffffffffu, wi, o);
            if (lane >= o) wi += n;
        }
        wsum[lane] = wi - wv;   // exclusive warp base
    }
    __syncthreads();

    int run = wsum[wid] + (incl - s);   // exclusive prefix for this thread
#pragma unroll
    for (int i = 0; i < 8; i++) {
        g_off[a][t * 8 + i] = run;
        g_cur[a][t * 8 + i] = run;
        run += c[i];
    }
    if (t == 1023) g_off[a][NB] = run;  // == NELEM
}

// ---------------------------------------------------------------------------
// 4) Scatter values into bucket order (within-bucket order is arbitrary;
//    min-over-bucket and the fixed-order final reduction are order-invariant,
//    so the kernel output is deterministic).
// ---------------------------------------------------------------------------
__global__ void scatter_kernel(const float* __restrict__ x,
                               const float* __restrict__ y) {
    const int i = blockIdx.x * blockDim.x + threadIdx.x;   // 0..32767
    const int a = (i >= NELEM);
    const float v = a ? y[i - NELEM] : x[i];
    const int b = bucket_of(v);
    const int p = atomicAdd(&g_cur[a][b], 1);
    g_bval[a][p] = v;
}

// ---------------------------------------------------------------------------
// 5) For each query value, expanding-ring bucket scan with an exact
//    lower-bound stopping rule. Queries iterate the ORIGINAL input order so
//    the per-block partial sums are bit-deterministic.
//    gid < NELEM : query x[gid] against y-buckets (cd_xy)
//    gid >= NELEM: query y[gid-N] against x-buckets (cd_yx)
// ---------------------------------------------------------------------------
__global__ void search_kernel(const float* __restrict__ x,
                              const float* __restrict__ y) {
    const int gid = blockIdx.x * blockDim.x + threadIdx.x;  // 0..32767
    const int qy = (gid >= NELEM);
    const float v = qy ? y[gid - NELEM] : x[gid];
    const int a = qy ? 0 : 1;                               // search opposite array
    const int*   __restrict__ off  = g_off[a];
    const float* __restrict__ vals = g_bval[a];

    const int b = bucket_of(v);
    float best = 3.4e38f;
    for (int i = off[b]; i < off[b + 1]; i++)
        best = fminf(best, fabsf(vals[i] - v));

    int l = b, r = b;
    while (true) {
        // Unscanned left buckets hold values < RANGE_LO + l*BW  -> dist >= v - that edge.
        // Unscanned right buckets hold values >= RANGE_LO + (r+1)*BW.
        const float lbL = (l > 0)      ? (v - (RANGE_LO + (float)l * BW))       : 3.4e38f;
        const float lbR = (r < NB - 1) ? ((RANGE_LO + (float)(r + 1) * BW) - v) : 3.4e38f;
        if (best <= fminf(lbL, lbR)) break;   // also terminates when both rails exhausted (lb = INF)
        if (l > 0) {
            l--;
            for (int i = off[l]; i < off[l + 1]; i++)
                best = fminf(best, fabsf(vals[i] - v));
        }
        if (r < NB - 1) {
            r++;
            for (int i = off[r]; i < off[r + 1]; i++)
                best = fminf(best, fabsf(vals[i] - v));
        }
    }

    // deterministic block reduction
    float d = best;
#pragma unroll
    for (int o = 16; o; o >>= 1) d += __shfl_xor_sync(0xffffffffu, d, o);
    __shared__ float ws[8];
    if ((threadIdx.x & 31) == 0) ws[threadIdx.x >> 5] = d;
    __syncthreads();
    if (threadIdx.x == 0) {
        float sum = 0.f;
#pragma unroll
        for (int i = 0; i < 8; i++) sum += ws[i];
        g_partials[blockIdx.x] = sum;
    }
}

// ---------------------------------------------------------------------------
// 6) Reduce 128 partials; ALPHA=0.5, n=m=16384 -> 0.5*(sx+sy)/16384.
// ---------------------------------------------------------------------------
__global__ void finalize_kernel(float* __restrict__ out) {
    const int t = threadIdx.x;   // 128 threads
    float v = g_partials[t];
#pragma unroll
    for (int o = 16; o; o >>= 1) v += __shfl_xor_sync(0xffffffffu, v, o);
    __shared__ float ws[4];
    if ((t & 31) == 0) ws[t >> 5] = v;
    __syncthreads();
    if (t == 0)
        out[0] = 0.5f * (ws[0] + ws[1] + ws[2] + ws[3]) * (1.0f / 16384.0f);
}

// ---------------------------------------------------------------------------
extern "C" void kernel_launch(void* const* d_in, const int* in_sizes, int n_in,
                              void* d_out, int out_size) {
    const float* x = (const float*)d_in[0];
    const float* y = (const float*)d_in[1];
    float* out = (float*)d_out;

    init_kernel<<<NB / 256, 256>>>();
    hist_kernel<<<2 * NELEM / 256, 256>>>(x, y);
    prefix_kernel<<<2, 1024>>>();
    scatter_kernel<<<2 * NELEM / 256, 256>>>(x, y);
    search_kernel<<<2 * NELEM / 256, 256>>>(x, y);
    finalize_kernel<<<1, 128>>>(out);
}

// round 6
// speedup vs baseline: 2.3243x; 1.0123x over previous
#include <cuda_runtime.h>

#define NELEM 16384
#define NB 8192                       // buckets per array (power of two)
#define NBLK 128                      // <= 148 SMs -> whole grid co-resident (spin barriers safe)
#define NTHR 256
#define RANGE_LO (-6.0f)
#define RANGE_HI (6.0f)
#define BW ((RANGE_HI - RANGE_LO) / (float)NB)
#define INV_BW ((float)NB / (RANGE_HI - RANGE_LO))

// Scratch (device globals; no allocations allowed). Zero-initialized at load;
// the kernel leaves every mutable field zeroed on exit so graph replays see
// identical initial state.
__device__ int            g_cnt[2][NB];      // hist counters (also yield ranks)
__device__ int            g_off[2][NB + 1];  // bucket offsets
__device__ float          g_bval[2][NELEM];  // bucketed values
__device__ float          g_partials[NBLK];
__device__ volatile int   g_bar[3];          // grid-barrier arrival counters
__device__ int            g_done;            // final-reduction arrival counter

__device__ __forceinline__ int bucket_of(float v) {
    int b = (int)((v - RANGE_LO) * INV_BW);
    return min(max(b, 0), NB - 1);    // clamp outliers; stop-bounds stay valid
}

// Single-use-per-launch grid barrier (reset by the last block at kernel end).
// All 128 CTAs are resident simultaneously, so spinning cannot deadlock.
__device__ __forceinline__ void grid_barrier(int slot) {
    __syncthreads();
    if (threadIdx.x == 0) {
        __threadfence();
        atomicAdd((int*)&g_bar[slot], 1);
        while (g_bar[slot] < NBLK) __nanosleep(32);
        __threadfence();
    }
    __syncthreads();
}

__global__ void __launch_bounds__(NTHR, 1)
chamfer_fused_kernel(const float* __restrict__ x,
                     const float* __restrict__ y,
                     float* __restrict__ out) {
    const int tid = threadIdx.x;
    const int gid = blockIdx.x * NTHR + tid;     // 0..32767
    const int a   = (gid >= NELEM);              // which array owns this element
    const int idx = a ? (gid - NELEM) : gid;
    const float v = a ? y[idx] : x[idx];
    const int  b  = bucket_of(v);

    // ---- Phase A: histogram; returned value = within-bucket rank -----------
    const int rank = atomicAdd(&g_cnt[a][b], 1);
    grid_barrier(0);

    // ---- Phase B: exclusive prefix over 8192 counts (blocks 0 and 1) -------
    if (blockIdx.x < 2) {
        const int arr  = blockIdx.x;
        const int lane = tid & 31, wid = tid >> 5;
        int c[32], s = 0;
#pragma unroll
        for (int i = 0; i < 32; i++) { c[i] = g_cnt[arr][tid * 32 + i]; s += c[i]; }

        int incl = s;                              // inclusive warp scan
#pragma unroll
        for (int o = 1; o < 32; o <<= 1) {
            int n = __shfl_up_sync(0xffffffffu, incl, o);
            if (lane >= o) incl += n;
        }
        __shared__ int wsum[8];
        if (lane == 31) wsum[wid] = incl;
        __syncthreads();
        if (tid == 0) {
            int run = 0;
#pragma unroll
            for (int w = 0; w < 8; w++) { int t2 = wsum[w]; wsum[w] = run; run += t2; }
        }
        __syncthreads();
        int run = wsum[wid] + (incl - s);          // exclusive prefix for this thread
#pragma unroll
        for (int i = 0; i < 32; i++) { g_off[arr][tid * 32 + i] = run; run += c[i]; }
        if (tid == NTHR - 1) g_off[arr][NB] = run; // == NELEM
    }
    grid_barrier(1);

    // ---- Phase C: scatter (no atomic: position = off[b] + rank) ------------
    g_bval[a][g_off[a][b] + rank] = v;
    // Counters are dead now; zero them for the next replay (16384 ints).
    if (gid < NB)            g_cnt[0][gid] = 0;
    else if (gid < 2 * NB)   g_cnt[1][gid - NB] = 0;
    grid_barrier(2);

    // ---- Phase D: expanding-ring nearest-neighbor search -------------------
    // gid < N: query x[gid] vs y-buckets; gid >= N: query y vs x-buckets.
    {
        const int sa = 1 - a;                      // search the opposite array
        const int*   __restrict__ off  = g_off[sa];
        const float* __restrict__ vals = g_bval[sa];

        float best = 3.4e38f;
        for (int i = off[b]; i < off[b + 1]; i++)
            best = fminf(best, fabsf(vals[i] - v));

        int l = b, r = b;
        while (true) {
            const float lbL = (l > 0)      ? (v - (RANGE_LO + (float)l * BW))       : 3.4e38f;
            const float lbR = (r < NB - 1) ? ((RANGE_LO + (float)(r + 1) * BW) - v) : 3.4e38f;
            if (best <= fminf(lbL, lbR)) break;    // exact stop; INF rails terminate too
            if (l > 0) {
                l--;
                for (int i = off[l]; i < off[l + 1]; i++)
                    best = fminf(best, fabsf(vals[i] - v));
            }
            if (r < NB - 1) {
                r++;
                for (int i = off[r]; i < off[r + 1]; i++)
                    best = fminf(best, fabsf(vals[i] - v));
            }
        }

        // deterministic block reduction
        float d = best;
#pragma unroll
        for (int o = 16; o; o >>= 1) d += __shfl_xor_sync(0xffffffffu, d, o);
        __shared__ float ws[8];
        if ((tid & 31) == 0) ws[tid >> 5] = d;
        __syncthreads();
        if (tid == 0) {
            float sum = 0.f;
#pragma unroll
            for (int i = 0; i < 8; i++) sum += ws[i];
            g_partials[blockIdx.x] = sum;
            __threadfence();
            // Last-done block: fixed-order final reduction (deterministic),
            // then reset all inter-launch state for the next graph replay.
            if (atomicAdd(&g_done, 1) == NBLK - 1) {
                __threadfence();
                float tot = 0.f;
                for (int i = 0; i < NBLK; i++) tot += g_partials[i];
                out[0] = 0.5f * tot * (1.0f / 16384.0f);  // ALPHA=0.5, n=m=16384
                g_bar[0] = 0; g_bar[1] = 0; g_bar[2] = 0;
                g_done = 0;
            }
        }
    }
}

// ---------------------------------------------------------------------------
extern "C" void kernel_launch(void* const* d_in, const int* in_sizes, int n_in,
                              void* d_out, int out_size) {
    const float* x = (const float*)d_in[0];
    const float* y = (const float*)d_in[1];
    float* out = (float*)d_out;
    chamfer_fused_kernel<<<NBLK, NTHR>>>(x, y, out);
}

// round 10
// speedup vs baseline: 3.5255x; 1.5168x over previous
#include <cuda_runtime.h>

#define NELEM 16384
#define NB 8192                       // buckets per array (power of two)
#define NBLK 128                      // <= 148 SMs -> whole grid co-resident (spin barriers safe)
#define NTHR 256
#define RANGE_LO (-6.0f)
#define RANGE_HI (6.0f)
#define INV_BW ((float)NB / (RANGE_HI - RANGE_LO))

// Scratch (device globals; no allocations allowed). Zero-initialized at load;
// the kernel leaves every mutable field zeroed on exit so graph replays see
// identical initial state.
__device__ int            g_cnt[2][NB];      // hist counters (atomic return = rank)
__device__ int            g_off[2][NB + 1];  // bucket offsets
__device__ float          g_bval[2][NELEM];  // bucketed values
__device__ float          g_partials[NBLK];
__device__ volatile int   g_bar[3];          // grid-barrier arrival counters
__device__ int            g_done;            // final-reduction arrival counter

__device__ __forceinline__ int bucket_of(float v) {
    int b = (int)((v - RANGE_LO) * INV_BW);
    return min(max(b, 0), NB - 1);    // clamp outliers into end buckets
}

// Grid barrier (reset by the last block at kernel end). All 128 CTAs are
// resident simultaneously, so spinning cannot deadlock.
__device__ __forceinline__ void grid_barrier(int slot) {
    __syncthreads();
    if (threadIdx.x == 0) {
        __threadfence();
        atomicAdd((int*)&g_bar[slot], 1);
        while (g_bar[slot] < NBLK) __nanosleep(32);
        __threadfence();
    }
    __syncthreads();
}

__global__ void __launch_bounds__(NTHR, 1)
chamfer_fused_kernel(const float* __restrict__ x,
                     const float* __restrict__ y,
                     float* __restrict__ out) {
    const int tid = threadIdx.x;
    const int gid = blockIdx.x * NTHR + tid;     // 0..32767
    const int a   = (gid >= NELEM);              // which array owns this element
    const int idx = a ? (gid - NELEM) : gid;
    const float v = a ? y[idx] : x[idx];
    const int  b  = bucket_of(v);

    // ---- Phase A: histogram; returned value = within-bucket rank -----------
    const int rank = atomicAdd(&g_cnt[a][b], 1);
    grid_barrier(0);

    // ---- Phase B: exclusive prefix over 8192 counts (blocks 0 and 1) -------
    if (blockIdx.x < 2) {
        const int arr  = blockIdx.x;
        const int lane = tid & 31, wid = tid >> 5;
        int c[32], s = 0;
        const int4* cv = reinterpret_cast<const int4*>(&g_cnt[arr][tid * 32]);
#pragma unroll
        for (int i = 0; i < 8; i++) {
            int4 t4 = cv[i];
            c[i * 4 + 0] = t4.x; c[i * 4 + 1] = t4.y;
            c[i * 4 + 2] = t4.z; c[i * 4 + 3] = t4.w;
            s += t4.x + t4.y + t4.z + t4.w;
        }

        int incl = s;                              // inclusive warp scan
#pragma unroll
        for (int o = 1; o < 32; o <<= 1) {
            int n = __shfl_up_sync(0xffffffffu, incl, o);
            if (lane >= o) incl += n;
        }
        __shared__ int wsum[8];
        if (lane == 31) wsum[wid] = incl;
        __syncthreads();
        if (tid == 0) {
            int run = 0;
#pragma unroll
            for (int w = 0; w < 8; w++) { int t2 = wsum[w]; wsum[w] = run; run += t2; }
        }
        __syncthreads();
        int run = wsum[wid] + (incl - s);          // exclusive prefix for this thread
#pragma unroll
        for (int i = 0; i < 32; i++) { g_off[arr][tid * 32 + i] = run; run += c[i]; }
        if (tid == NTHR - 1) g_off[arr][NB] = run; // == NELEM
    }
    grid_barrier(1);

    // ---- Phase C: scatter (no atomic: position = off[b] + rank) ------------
    g_bval[a][g_off[a][b] + rank] = v;
    // Counters are dead now; zero them for the next graph replay.
    if (gid < NB)            g_cnt[0][gid] = 0;
    else if (gid < 2 * NB)   g_cnt[1][gid - NB] = 0;
    grid_barrier(2);

    // ---- Phase D: EXACT 3-bucket nearest-neighbor lookup (no loops over
    //      empty buckets). The bucketed array is value-ordered up to
    //      within-bucket permutation, so:
    //        pred(v) is in bucket b, or in bucket_of(vals[off[b]-1])
    //        succ(v) is in bucket b, or in bucket_of(vals[off[b+1]])
    //      Min over those <=3 fully-scanned buckets == exact NN distance.
    {
        const int sa = 1 - a;                      // search the opposite array
        const int*   __restrict__ off  = g_off[sa];
        const float* __restrict__ vals = g_bval[sa];

        const int p = off[b];
        const int q = off[b + 1];

        float best = 3.4e38f;
        for (int i = p; i < q; i++)
            best = fminf(best, fabsf(vals[i] - v));

        if (p > 0) {                               // nearest non-empty bucket below
            const int bl = bucket_of(vals[p - 1]);
            const int e  = off[bl + 1];            // == p
            for (int i = off[bl]; i < e; i++)
                best = fminf(best, fabsf(vals[i] - v));
        }
        if (q < NELEM) {                           // nearest non-empty bucket above
            const int br = bucket_of(vals[q]);
            const int e  = off[br + 1];
            for (int i = off[br]; i < e; i++)
                best = fminf(best, fabsf(vals[i] - v));
        }

        // deterministic block reduction
        float d = best;
#pragma unroll
        for (int o = 16; o; o >>= 1) d += __shfl_xor_sync(0xffffffffu, d, o);
        __shared__ float ws[8];
        if ((tid & 31) == 0) ws[tid >> 5] = d;
        __syncthreads();
        if (tid == 0) {
            float sum = 0.f;
#pragma unroll
            for (int i = 0; i < 8; i++) sum += ws[i];
            g_partials[blockIdx.x] = sum;
            __threadfence();
            // Last-done block: fixed-order final reduction (deterministic),
            // then reset all inter-launch state for the next graph replay.
            if (atomicAdd(&g_done, 1) == NBLK - 1) {
                __threadfence();
                float tot = 0.f;
                for (int i = 0; i < NBLK; i++) tot += g_partials[i];
                out[0] = 0.5f * tot * (1.0f / 16384.0f);  // ALPHA=0.5, n=m=16384
                g_bar[0] = 0; g_bar[1] = 0; g_bar[2] = 0;
                g_done = 0;
            }
        }
    }
}

// ---------------------------------------------------------------------------
extern "C" void kernel_launch(void* const* d_in, const int* in_sizes, int n_in,
                              void* d_out, int out_size) {
    const float* x = (const float*)d_in[0];
    const float* y = (const float*)d_in[1];
    float* out = (float*)d_out;
    chamfer_fused_kernel<<<NBLK, NTHR>>>(x, y, out);
}

// round 11
// speedup vs baseline: 4.7660x; 1.3519x over previous
#include <cuda_runtime.h>

#define NELEM 16384
#define NB 8192                       // buckets per array (power of two)
#define NBW (NB / 32)                 // bitmask words per array
#define CAP 16                        // slots per bucket (Poisson lambda=2 -> overflow ~1e-9)
#define NBLK 128                      // <= 148 SMs -> whole grid co-resident (spin barrier safe)
#define NTHR 256
#define RANGE_LO (-6.0f)
#define RANGE_HI (6.0f)
#define INV_BW ((float)NB / (RANGE_HI - RANGE_LO))

// Scratch (device globals; no allocations). Zero-initialized at load; the
// last-done block re-zeroes all mutable state so graph replays are identical.
__device__ int      g_cnt[2][NB];        // per-bucket counts (atomic rank source)
__device__ unsigned g_bits[2][NBW];      // non-empty bucket bitmask
__device__ float    g_slot[2][NB][CAP];  // bucket slots
__device__ int      g_ovf_cnt[2];        // overflow counts (normally 0)
__device__ float    g_ovf[2][NELEM];     // overflow values (worst-case capacity)
__device__ float    g_partials[NBLK];
__device__ volatile int g_bar;           // single grid barrier
__device__ int      g_done;              // completion counter

__device__ __forceinline__ int bucket_of(float v) {
    int b = (int)((v - RANGE_LO) * INV_BW);
    return min(max(b, 0), NB - 1);       // clamp outliers into end buckets
}

// highest set bit index < b, or -1
__device__ __forceinline__ int prev_ne(const unsigned* __restrict__ bits, int b) {
    int w = b >> 5;
    unsigned m = bits[w] & ((1u << (b & 31)) - 1u);   // bits strictly below b
    while (true) {
        if (m) return (w << 5) + 31 - __clz(m);
        if (--w < 0) return -1;
        m = bits[w];
    }
}
// lowest set bit index > b, or -1
__device__ __forceinline__ int next_ne(const unsigned* __restrict__ bits, int b) {
    int w = b >> 5;
    const int r = b & 31;
    unsigned m = bits[w] & ((r == 31) ? 0u : (0xFFFFFFFFu << (r + 1)));  // bits strictly above b
    while (true) {
        if (m) return (w << 5) + __ffs(m) - 1;
        if (++w >= NBW) return -1;
        m = bits[w];
    }
}

__global__ void __launch_bounds__(NTHR, 1)
chamfer_fused_kernel(const float* __restrict__ x,
                     const float* __restrict__ y,
                     float* __restrict__ out) {
    const int tid = threadIdx.x;
    const int gid = blockIdx.x * NTHR + tid;     // 0..32767
    const int a   = (gid >= NELEM);              // owning array
    const int idx = a ? (gid - NELEM) : gid;
    const float v = a ? __ldg(&y[idx]) : __ldg(&x[idx]);
    const int  b  = bucket_of(v);

    // ---- Phase A: fused histogram + scatter + bitmask -----------------------
    const int rank = atomicAdd(&g_cnt[a][b], 1);
    if (rank < CAP) {
        g_slot[a][b][rank] = v;
        if (rank == 0) atomicOr(&g_bits[a][b >> 5], 1u << (b & 31));
    } else {
        const int o = atomicAdd(&g_ovf_cnt[a], 1);
        g_ovf[a][o] = v;
    }

    // ---- single grid barrier (all 128 CTAs co-resident; cannot deadlock) ----
    __syncthreads();
    if (tid == 0) {
        __threadfence();
        atomicAdd((int*)&g_bar, 1);
        while (g_bar < NBLK) __nanosleep(32);
        __threadfence();
    }
    __syncthreads();

    // ---- Phase B: exact <=3-bucket NN lookup via bitmask skip ----------------
    // Scanning own bucket + nearest non-empty bucket below + above fully
    // covers pred(v) and succ(v). Overflowed values live in g_ovf, which every
    // query scans; extra scanned values are real elements so the min is exact.
    float best = 3.4e38f;
    {
        const int sa = 1 - a;
        const int*      __restrict__ cnt  = g_cnt[sa];
        const unsigned* __restrict__ bits = g_bits[sa];

        int c = min(cnt[b], CAP);
        for (int i = 0; i < c; i++)
            best = fminf(best, fabsf(g_slot[sa][b][i] - v));

        const int bl = prev_ne(bits, b);
        if (bl >= 0) {
            c = min(cnt[bl], CAP);
            for (int i = 0; i < c; i++)
                best = fminf(best, fabsf(g_slot[sa][bl][i] - v));
        }
        const int br = next_ne(bits, b);
        if (br >= 0) {
            c = min(cnt[br], CAP);
            for (int i = 0; i < c; i++)
                best = fminf(best, fabsf(g_slot[sa][br][i] - v));
        }
        const int oc = g_ovf_cnt[sa];                 // normally 0
        for (int i = 0; i < oc; i++)
            best = fminf(best, fabsf(g_ovf[sa][i] - v));
    }

    // ---- deterministic block reduction --------------------------------------
    float d = best;
#pragma unroll
    for (int o = 16; o; o >>= 1) d += __shfl_xor_sync(0xffffffffu, d, o);
    __shared__ float ws[8];
    __shared__ int   last;
    if ((tid & 31) == 0) ws[tid >> 5] = d;
    __syncthreads();
    if (tid == 0) {
        float sum = 0.f;
#pragma unroll
        for (int i = 0; i < 8; i++) sum += ws[i];
        g_partials[blockIdx.x] = sum;
        __threadfence();
        last = (atomicAdd(&g_done, 1) == NBLK - 1);
    }
    __syncthreads();

    // ---- last-done block: reset state + fixed-order final reduction ---------
    if (last) {
        // zero counters/bitmask/overflow for the next graph replay
        for (int i = tid; i < 2 * NB; i += NTHR) g_cnt[i >= NB][i & (NB - 1)] = 0;
        for (int i = tid; i < 2 * NBW; i += NTHR) g_bits[i >= NBW][i & (NBW - 1)] = 0;
        if (tid == 0) { g_ovf_cnt[0] = 0; g_ovf_cnt[1] = 0; }
        if (tid == 0) {
            __threadfence();
            float tot = 0.f;
            for (int i = 0; i < NBLK; i++) tot += g_partials[i];  // fixed order
            out[0] = 0.5f * tot * (1.0f / 16384.0f);  // ALPHA=0.5, n=m=16384
            g_bar = 0;
            g_done = 0;
        }
    }
}

// ---------------------------------------------------------------------------
extern "C" void kernel_launch(void* const* d_in, const int* in_sizes, int n_in,
                              void* d_out, int out_size) {
    const float* x = (const float*)d_in[0];
    const float* y = (const float*)d_in[1];
    float* out = (float*)d_out;
    chamfer_fused_kernel<<<NBLK, NTHR>>>(x, y, out);
}

// round 12
// speedup vs baseline: 4.7902x; 1.0051x over previous
#include <cuda_runtime.h>

#define NELEM 16384
#define NB 8192                       // buckets per array (power of two)
#define NBW (NB / 32)                 // bitmask words per array (256)
#define CAP 16                        // slots per bucket (lambda=2 -> P(>=16) ~ 1e-9)
#define NBLK 128                      // <= 148 SMs -> whole grid co-resident (spin barrier safe)
#define NTHR 256
#define RANGE_LO (-6.0f)
#define RANGE_HI (6.0f)
#define INV_BW ((float)NB / (RANGE_HI - RANGE_LO))

// Scratch (device globals; no allocations). Zero-initialized at load; the
// last-done block re-zeroes all mutable state so graph replays are identical.
// Slots beyond a bucket's final count are NEVER written in any replay (same
// input -> same counts), so unconditional slot reads see zero-init data that
// the idx<cnt mask discards.
__device__ int      g_cnt[2][NB];        // per-bucket counts (atomic rank source)
__device__ unsigned g_bits[2][NBW];      // non-empty bucket bitmask
__device__ float    g_slot[2][NB][CAP];  // bucket slots (64B-aligned per bucket)
__device__ int      g_ovf_cnt[2];        // overflow counts (normally 0)
__device__ float    g_ovf[2][NELEM];     // overflow values (worst-case capacity)
__device__ float    g_partials[NBLK];
__device__ volatile int g_bar;           // single grid barrier
__device__ int      g_done;              // completion counter

__device__ __forceinline__ int bucket_of(float v) {
    int b = (int)((v - RANGE_LO) * INV_BW);
    return min(max(b, 0), NB - 1);       // clamp outliers into end buckets
}

// Unconditional vectorized bucket scan: 4x LDG.128 issued in parallel with the
// cnt load; elements at index >= c are masked out.
__device__ __forceinline__ float scan_bucket(int sa, int bkt, float v, float best) {
    const int c = min(g_cnt[sa][bkt], CAP);
    const float4* sv = reinterpret_cast<const float4*>(g_slot[sa][bkt]);
#pragma unroll
    for (int k = 0; k < 4; k++) {
        const float4 s = sv[k];
        const int i0 = k * 4;
        if (i0 + 0 < c) best = fminf(best, fabsf(s.x - v));
        if (i0 + 1 < c) best = fminf(best, fabsf(s.y - v));
        if (i0 + 2 < c) best = fminf(best, fabsf(s.z - v));
        if (i0 + 3 < c) best = fminf(best, fabsf(s.w - v));
    }
    return best;
}

// highest set bit index < b, or -1 (smem bitmask)
__device__ __forceinline__ int prev_ne(const unsigned* bits, int b) {
    int w = b >> 5;
    unsigned m = bits[w] & ((1u << (b & 31)) - 1u);
    while (true) {
        if (m) return (w << 5) + 31 - __clz(m);
        if (--w < 0) return -1;
        m = bits[w];
    }
}
// lowest set bit index > b, or -1 (smem bitmask)
__device__ __forceinline__ int next_ne(const unsigned* bits, int b) {
    int w = b >> 5;
    const int r = b & 31;
    unsigned m = bits[w] & ((r == 31) ? 0u : (0xFFFFFFFFu << (r + 1)));
    while (true) {
        if (m) return (w << 5) + __ffs(m) - 1;
        if (++w >= NBW) return -1;
        m = bits[w];
    }
}

__global__ void __launch_bounds__(NTHR, 1)
chamfer_fused_kernel(const float* __restrict__ x,
                     const float* __restrict__ y,
                     float* __restrict__ out) {
    __shared__ unsigned sbits[NBW];   // opposite array's non-empty bitmask (1KB)
    __shared__ float    ws[8];
    __shared__ int      last;

    const int tid = threadIdx.x;
    const int gid = blockIdx.x * NTHR + tid;     // 0..32767
    const int a   = (gid >= NELEM);              // uniform per block (64/64 split)
    const int idx = a ? (gid - NELEM) : gid;
    const float v = a ? __ldg(&y[idx]) : __ldg(&x[idx]);
    const int  b  = bucket_of(v);

    // ---- Phase A: fused histogram + scatter + bitmask -----------------------
    // atomicOr first: independent of the rank return, so it overlaps the
    // atomicAdd round-trip instead of serializing behind it.
    atomicOr(&g_bits[a][b >> 5], 1u << (b & 31));
    const int rank = atomicAdd(&g_cnt[a][b], 1);
    if (rank < CAP) {
        g_slot[a][b][rank] = v;
    } else {
        const int o = atomicAdd(&g_ovf_cnt[a], 1);
        g_ovf[a][o] = v;
    }

    // ---- single grid barrier (all 128 CTAs co-resident; pure spin) ----------
    __syncthreads();
    if (tid == 0) {
        __threadfence();
        atomicAdd((int*)&g_bar, 1);
        while (g_bar < NBLK) { }
        __threadfence();
    }
    __syncthreads();

    // ---- Phase B: exact <=3-bucket NN lookup ---------------------------------
    const int sa = 1 - a;

    // Stage opposite bitmask to smem (one coalesced word per thread).
    sbits[tid] = g_bits[sa][tid];
    // Own-bucket scan issues before the staging sync (doesn't need sbits).
    float best = scan_bucket(sa, b, v, 3.4e38f);
    __syncthreads();

    const int bl = prev_ne(sbits, b);
    const int br = next_ne(sbits, b);
    if (bl >= 0) best = scan_bucket(sa, bl, v, best);
    if (br >= 0) best = scan_bucket(sa, br, v, best);

    const int oc = g_ovf_cnt[sa];                 // normally 0
    for (int i = 0; i < oc; i++)
        best = fminf(best, fabsf(g_ovf[sa][i] - v));

    // ---- deterministic block reduction --------------------------------------
    float d = best;
#pragma unroll
    for (int o = 16; o; o >>= 1) d += __shfl_xor_sync(0xffffffffu, d, o);
    if ((tid & 31) == 0) ws[tid >> 5] = d;
    __syncthreads();
    if (tid == 0) {
        float sum = 0.f;
#pragma unroll
        for (int i = 0; i < 8; i++) sum += ws[i];
        g_partials[blockIdx.x] = sum;
        __threadfence();
        last = (atomicAdd(&g_done, 1) == NBLK - 1);
    }
    __syncthreads();

    // ---- last-done block: reset state + fixed-order final reduction ---------
    // Safe: every other block's g_done increment happens after all its reads.
    if (last) {
        // cnt: 2*NB ints = 4096 int4; bits: 2*NBW words = 128 int4
        int4* cz = reinterpret_cast<int4*>(g_cnt);
        for (int i = tid; i < (2 * NB) / 4; i += NTHR) cz[i] = make_int4(0, 0, 0, 0);
        int4* bz = reinterpret_cast<int4*>(g_bits);
        for (int i = tid; i < (2 * NBW) / 4; i += NTHR) bz[i] = make_int4(0, 0, 0, 0);
        if (tid == 0) {
            g_ovf_cnt[0] = 0; g_ovf_cnt[1] = 0;
            __threadfence();
            float tot = 0.f;
            for (int i = 0; i < NBLK; i++) tot += g_partials[i];  // fixed order
            out[0] = 0.5f * tot * (1.0f / 16384.0f);  // ALPHA=0.5, n=m=16384
            g_bar = 0;
            g_done = 0;
        }
    }
}

// ---------------------------------------------------------------------------
extern "C" void kernel_launch(void* const* d_in, const int* in_sizes, int n_in,
                              void* d_out, int out_size) {
    const float* x = (const float*)d_in[0];
    const float* y = (const float*)d_in[1];
    float* out = (float*)d_out;
    chamfer_fused_kernel<<<NBLK, NTHR>>>(x, y, out);
}

// round 13
// speedup vs baseline: 5.1945x; 1.0844x over previous
#include <cuda_runtime.h>

#define NELEM 16384
#define NB 8192                       // buckets per array (power of two)
#define NBW (NB / 32)                 // bitmask words per array (256)
#define CAP 16                        // slots per bucket (lambda=2 -> P(>16) ~ 1e-10)
#define NBLK 64                       // co-resident grid (64 <= 148 SMs) -> spin barrier safe
#define NTHR 512                      // 16 warps/SM for latency hiding
#define RANGE_LO (-6.0f)
#define RANGE_HI (6.0f)
#define INV_BW ((float)NB / (RANGE_HI - RANGE_LO))

// Scratch (device globals; no allocations). Zero-initialized at load; the
// last-done block re-zeroes all mutable state so graph replays are identical.
// Slots beyond a bucket's final count are NEVER written in any replay (same
// input -> same counts), so unconditional slot reads see zero-init data that
// the idx<cnt mask discards.
__device__ int      g_cnt[2][NB];        // per-bucket counts (atomic rank source)
__device__ unsigned g_bits[2][NBW];      // non-empty bucket bitmask
__device__ float    g_slot[2][NB][CAP];  // bucket slots (64B-aligned per bucket)
__device__ int      g_ovf_cnt[2];        // overflow counts (normally 0)
__device__ float    g_ovf[2][NELEM];     // overflow values (worst-case capacity)
__device__ float    g_partials[NBLK];
__device__ volatile int g_bar;           // single grid barrier
__device__ int      g_done;              // completion counter

__device__ __forceinline__ int bucket_of(float v) {
    int b = (int)((v - RANGE_LO) * INV_BW);
    return min(max(b, 0), NB - 1);       // clamp outliers into end buckets
}

// Vectorized bucket scan. Slots 0..7 unconditional (2x LDG.128 issued in
// parallel with the cnt load); slots 8..15 only for the ~0.02% of buckets
// with c>8 (rare, near-uniform branch).
__device__ __forceinline__ float scan_bucket(int sa, int bkt, float v, float best) {
    const int c = min(g_cnt[sa][bkt], CAP);
    const float4* sv = reinterpret_cast<const float4*>(g_slot[sa][bkt]);
#pragma unroll
    for (int k = 0; k < 2; k++) {
        const float4 s = sv[k];
        const int i0 = k * 4;
        if (i0 + 0 < c) best = fminf(best, fabsf(s.x - v));
        if (i0 + 1 < c) best = fminf(best, fabsf(s.y - v));
        if (i0 + 2 < c) best = fminf(best, fabsf(s.z - v));
        if (i0 + 3 < c) best = fminf(best, fabsf(s.w - v));
    }
    if (c > 8) {
#pragma unroll
        for (int k = 2; k < 4; k++) {
            const float4 s = sv[k];
            const int i0 = k * 4;
            if (i0 + 0 < c) best = fminf(best, fabsf(s.x - v));
            if (i0 + 1 < c) best = fminf(best, fabsf(s.y - v));
            if (i0 + 2 < c) best = fminf(best, fabsf(s.z - v));
            if (i0 + 3 < c) best = fminf(best, fabsf(s.w - v));
        }
    }
    return best;
}

// highest set bit index < b, or -1 (smem bitmask; 32-bucket stride skip)
__device__ __forceinline__ int prev_ne(const unsigned* bits, int b) {
    int w = b >> 5;
    unsigned m = bits[w] & ((1u << (b & 31)) - 1u);
    while (true) {
        if (m) return (w << 5) + 31 - __clz(m);
        if (--w < 0) return -1;
        m = bits[w];
    }
}
// lowest set bit index > b, or -1 (smem bitmask)
__device__ __forceinline__ int next_ne(const unsigned* bits, int b) {
    int w = b >> 5;
    const int r = b & 31;
    unsigned m = bits[w] & ((r == 31) ? 0u : (0xFFFFFFFFu << (r + 1)));
    while (true) {
        if (m) return (w << 5) + __ffs(m) - 1;
        if (++w >= NBW) return -1;
        m = bits[w];
    }
}

__global__ void __launch_bounds__(NTHR, 1)
chamfer_fused_kernel(const float* __restrict__ x,
                     const float* __restrict__ y,
                     float* __restrict__ out) {
    __shared__ unsigned sbits[NBW];   // opposite array's non-empty bitmask (1KB)
    __shared__ float    ws[NTHR / 32];
    __shared__ float    fin[2];
    __shared__ int      last;

    const int tid = threadIdx.x;
    const int gid = blockIdx.x * NTHR + tid;     // 0..32767
    const int a   = (gid >= NELEM);              // uniform per block (32/32 split)
    const int idx = a ? (gid - NELEM) : gid;
    const float v = a ? __ldg(&y[idx]) : __ldg(&x[idx]);
    const int  b  = bucket_of(v);

    // ---- Phase A: fused histogram + scatter + bitmask -----------------------
    // atomicOr first: independent of the rank return, overlaps the atomicAdd
    // round-trip instead of serializing behind it.
    atomicOr(&g_bits[a][b >> 5], 1u << (b & 31));
    const int rank = atomicAdd(&g_cnt[a][b], 1);
    if (rank < CAP) {
        g_slot[a][b][rank] = v;
    } else {
        const int o = atomicAdd(&g_ovf_cnt[a], 1);
        g_ovf[a][o] = v;
    }

    // ---- single grid barrier (64 co-resident CTAs; pure spin) ---------------
    __syncthreads();
    if (tid == 0) {
        __threadfence();
        atomicAdd((int*)&g_bar, 1);
        while (g_bar < NBLK) { }
        __threadfence();
    }
    __syncthreads();

    // ---- Phase B: exact <=3-bucket NN lookup ---------------------------------
    const int sa = 1 - a;
    const int oc = g_ovf_cnt[sa];                 // issue early; normally 0

    // Stage opposite bitmask to smem (first 256 threads, one word each).
    if (tid < NBW) sbits[tid] = g_bits[sa][tid];
    // Own-bucket scan issues before the staging sync (doesn't need sbits).
    float best = scan_bucket(sa, b, v, 3.4e38f);
    __syncthreads();

    const int bl = prev_ne(sbits, b);
    const int br = next_ne(sbits, b);
    if (bl >= 0) best = scan_bucket(sa, bl, v, best);
    if (br >= 0) best = scan_bucket(sa, br, v, best);

    for (int i = 0; i < oc; i++)                  // normally zero iterations
        best = fminf(best, fabsf(g_ovf[sa][i] - v));

    // ---- deterministic block reduction (16 warps) ----------------------------
    float d = best;
#pragma unroll
    for (int o = 16; o; o >>= 1) d += __shfl_xor_sync(0xffffffffu, d, o);
    if ((tid & 31) == 0) ws[tid >> 5] = d;
    __syncthreads();
    if (tid == 0) {
        float sum = 0.f;
#pragma unroll
        for (int i = 0; i < NTHR / 32; i++) sum += ws[i];
        g_partials[blockIdx.x] = sum;
        __threadfence();
        last = (atomicAdd(&g_done, 1) == NBLK - 1);
    }
    __syncthreads();

    // ---- last-done block: final reduction (fixed tree, deterministic) + reset
    if (last) {
        if (tid < NBLK) {                          // 64 partials, 2 warps
            float p = g_partials[tid];
#pragma unroll
            for (int o = 16; o; o >>= 1) p += __shfl_xor_sync(0xffffffffu, p, o);
            if ((tid & 31) == 0) fin[tid >> 5] = p;
        }
        // reset state for the next graph replay (runs in parallel with above)
        int4* cz = reinterpret_cast<int4*>(g_cnt);
        for (int i = tid; i < (2 * NB) / 4; i += NTHR) cz[i] = make_int4(0, 0, 0, 0);
        int4* bz = reinterpret_cast<int4*>(g_bits);
        for (int i = tid; i < (2 * NBW) / 4; i += NTHR) bz[i] = make_int4(0, 0, 0, 0);
        __syncthreads();
        if (tid == 0) {
            out[0] = 0.5f * (fin[0] + fin[1]) * (1.0f / 16384.0f);  // ALPHA=0.5
            g_ovf_cnt[0] = 0; g_ovf_cnt[1] = 0;
            g_bar = 0;
            g_done = 0;
        }
    }
}

// ---------------------------------------------------------------------------
extern "C" void kernel_launch(void* const* d_in, const int* in_sizes, int n_in,
                              void* d_out, int out_size) {
    const float* x = (const float*)d_in[0];
    const float* y = (const float*)d_in[1];
    float* out = (float*)d_out;
    chamfer_fused_kernel<<<NBLK, NTHR>>>(x, y, out);
}